// round 8
// baseline (speedup 1.0000x reference)
#include <cuda_runtime.h>
#include <cstdint>

// Binary 3x3 conv, SAME pad, stride 1 — int8 tensor-core implicit GEMM.
// inputs: (32,56,56,256) f32 NHWC ; kernel: (3,3,256,256) f32 HWIO ; out: (32,56,56,256) f32
// sign() in {-1,0,+1} -> exact in s8; s32 accumulation -> bit-exact vs reference.
// sm_100-baseline ISA only: mma.sync m16n8k32 s8, ldmatrix, cp.async.
// R8 (= R7 resubmit): BM=64 (finer waves, 3.7% tail), register-double-buffered ldmatrix.

#define NB 32
#define HH 56
#define WW 56
#define CC 256
#define OO 256
#define PIX (NB*HH*WW)        // 100352
#define BM 64                 // pixels per CTA tile
#define NSTG 18               // 9 taps * 2 k-chunks of 128B
#define STAGE_BYTES 40960     // A 8KB + B 32KB
#define RING 4

__device__ int8_t g_X[(size_t)PIX * CC];      // sign(inputs)  [pix][c]
__device__ int8_t g_W[9 * OO * CC];           // sign(kernel)  [tap][o][c]

__device__ __forceinline__ uint32_t smem_u32(const void* p) {
    uint32_t a;
    asm("{ .reg .u64 t; cvta.to.shared.u64 t, %1; cvt.u32.u64 %0, t; }" : "=r"(a) : "l"(p));
    return a;
}
#define CP_ASYNC(dst, src, sz) \
    asm volatile("cp.async.cg.shared.global [%0], [%1], 16, %2;" :: "r"(dst), "l"(src), "r"(sz))
#define CP_COMMIT() asm volatile("cp.async.commit_group;" ::: "memory")
#define CP_WAIT(n)  asm volatile("cp.async.wait_group %0;" :: "n"(n))
#define LDSM4(r0, r1, r2, r3, a) \
    asm volatile("ldmatrix.sync.aligned.m8n8.x4.shared.b16 {%0,%1,%2,%3}, [%4];" \
                 : "=r"(r0), "=r"(r1), "=r"(r2), "=r"(r3) : "r"(a))
#define MMA(d, a, b0, b1) \
    asm volatile("mma.sync.aligned.m16n8k32.row.col.s32.s8.s8.s32 " \
                 "{%0,%1,%2,%3}, {%4,%5,%6,%7}, {%8,%9}, {%0,%1,%2,%3};" \
                 : "+r"((d)[0]), "+r"((d)[1]), "+r"((d)[2]), "+r"((d)[3]) \
                 : "r"((a)[0]), "r"((a)[1]), "r"((a)[2]), "r"((a)[3]), "r"(b0), "r"(b1))

// ---------------- prep kernels ----------------
__global__ void k_sign_x(const float* __restrict__ in) {
    size_t i = ((size_t)blockIdx.x * blockDim.x + threadIdx.x) * 16;
    int8_t o[16];
#pragma unroll
    for (int j = 0; j < 16; j += 4) {
        float4 v = *(const float4*)(in + i + j);
        o[j + 0] = v.x > 0.f ? 1 : (v.x < 0.f ? -1 : 0);
        o[j + 1] = v.y > 0.f ? 1 : (v.y < 0.f ? -1 : 0);
        o[j + 2] = v.z > 0.f ? 1 : (v.z < 0.f ? -1 : 0);
        o[j + 3] = v.w > 0.f ? 1 : (v.w < 0.f ? -1 : 0);
    }
    *(uint4*)(g_X + i) = *(uint4*)o;
}

// kernel HWIO [t][c][o] f32 -> g_W [t][o][c] s8
__global__ void k_sign_w(const float* __restrict__ kw) {
    int t = blockIdx.x >> 8;
    int c = blockIdx.x & 255;
    int o = threadIdx.x;
    float v = kw[((size_t)(t * CC + c)) * OO + o];     // coalesced in o
    g_W[((size_t)(t * OO + o)) * CC + c] = v > 0.f ? 1 : (v < 0.f ? -1 : 0);
}

// ---------------- stage loader ----------------
// Stage stg = tap*2 + kc. A: 64 rows(pixel) x 128B; B: 256 rows(o) x 128B.
// Smem rows are 128B with 16B-chunk XOR swizzle (chunk' = chunk ^ (row&7)).
struct AGeom { int n, y, x; int row, cb; };

__device__ __forceinline__ void load_stage(uint32_t sbase, const AGeom& ag,
                                           int stg, int tid) {
    const int tap = stg >> 1;
    const int kc = stg & 1;
    const uint32_t Ab = sbase + (stg & (RING - 1)) * STAGE_BYTES;
    const uint32_t Bb = Ab + 8192;

    // A: 64 rows x 8 chunks = 512 ops; thread -> row tid>>2, 2 chunks
    {
        const int yy = ag.y + tap / 3 - 1;
        const int xx = ag.x + tap % 3 - 1;
        const bool ok = (unsigned)yy < (unsigned)HH && (unsigned)xx < (unsigned)WW;
        const uint32_t sz = ok ? 16u : 0u;
        const int8_t* src = g_X +
            (ok ? ((size_t)((ag.n * HH + yy) * WW + xx)) * CC + kc * 128 : (size_t)0);
#pragma unroll
        for (int j = 0; j < 2; ++j) {
            const int c = ag.cb + j;
            CP_ASYNC(Ab + ag.row * 128 + 16 * (c ^ (ag.row & 7)), src + c * 16, sz);
        }
    }
    // B: 256 rows x 8 chunks; thread -> row o = tid
    {
        const int8_t* src = g_W + ((size_t)(tap * OO + tid)) * CC + kc * 128;
#pragma unroll
        for (int c = 0; c < 8; ++c)
            CP_ASYNC(Bb + tid * 128 + 16 * (c ^ (tid & 7)), src + c * 16, 16u);
    }
}

// ---------------- main conv kernel ----------------
// 1568 CTAs x 256 threads. 8 warps as 2(M) x 4(N); warp tile m32 x n64.
__global__ void __launch_bounds__(256, 1) k_conv(float* __restrict__ out) {
    extern __shared__ __align__(1024) char smem_raw[];
    const uint32_t sbase = smem_u32(smem_raw);
    const int tid = threadIdx.x;
    const int wid = tid >> 5;
    const int lane = tid & 31;
    const int tile = blockIdx.x;

    const int warp_m = wid >> 2;
    const int warp_n = wid & 3;
    const int lane7 = lane & 7;

    AGeom ag;
    ag.row = tid >> 2;
    ag.cb = (tid & 3) * 2;
    {
        const int gp = tile * BM + ag.row;
        ag.n = gp / (HH * WW);
        const int rem = gp % (HH * WW);
        ag.y = rem / WW;
        ag.x = rem % WW;
    }

    const int a_row = lane7 + ((lane >> 3) & 1) * 8;
    const int a_half = (lane >> 4) & 1;
    const int b_row = lane7 + ((lane >> 4) & 1) * 8;
    const int b_half = (lane >> 3) & 1;

    uint32_t aoff[2], boff[4];
#pragma unroll
    for (int mf = 0; mf < 2; ++mf) aoff[mf] = (warp_m * 32 + mf * 16 + a_row) * 128;
#pragma unroll
    for (int ng = 0; ng < 4; ++ng) boff[ng] = (warp_n * 64 + ng * 16 + b_row) * 128;

    int acc[2][8][4];
#pragma unroll
    for (int mf = 0; mf < 2; ++mf)
#pragma unroll
        for (int nf = 0; nf < 8; ++nf)
#pragma unroll
            for (int q = 0; q < 4; ++q) acc[mf][nf][q] = 0;

    // prologue: fill 3 stages
    load_stage(sbase, ag, 0, tid); CP_COMMIT();
    load_stage(sbase, ag, 1, tid); CP_COMMIT();
    load_stage(sbase, ag, 2, tid); CP_COMMIT();

    // register double buffers for fragments
    uint32_t a[2][2][4], b[2][4][4];

#define LD_FRAGS(ks, buf) do {                                                  \
        _Pragma("unroll")                                                       \
        for (int mf = 0; mf < 2; ++mf)                                          \
            LDSM4(a[buf][mf][0], a[buf][mf][1], a[buf][mf][2], a[buf][mf][3],   \
                  Ab + aoff[mf] + 16 * ((2 * (ks) + a_half) ^ lane7));          \
        _Pragma("unroll")                                                       \
        for (int ng = 0; ng < 4; ++ng)                                          \
            LDSM4(b[buf][ng][0], b[buf][ng][1], b[buf][ng][2], b[buf][ng][3],   \
                  Bb + boff[ng] + 16 * ((2 * (ks) + b_half) ^ lane7));          \
    } while (0)

    for (int it = 0; it < NSTG; ++it) {
        if (it < NSTG - 2)       CP_WAIT(2);
        else if (it == NSTG - 2) CP_WAIT(1);
        else                     CP_WAIT(0);
        __syncthreads();
        // Buffer (it-1)&3 is free here (all ldmatrix reads preceded the barrier).
        if (it + 3 < NSTG) {
            load_stage(sbase, ag, it + 3, tid);   // overlaps the MMA body below
            CP_COMMIT();
        }

        const uint32_t Ab = sbase + (it & (RING - 1)) * STAGE_BYTES;
        const uint32_t Bb = Ab + 8192;

        LD_FRAGS(0, 0);
#pragma unroll
        for (int ks = 0; ks < 4; ++ks) {
            if (ks < 3) LD_FRAGS(ks + 1, (ks + 1) & 1);   // prefetch next frags
            const int cur = ks & 1;
#pragma unroll
            for (int mf = 0; mf < 2; ++mf)
#pragma unroll
                for (int ng = 0; ng < 4; ++ng) {
                    MMA(acc[mf][2 * ng],     a[cur][mf], b[cur][ng][0], b[cur][ng][1]);
                    MMA(acc[mf][2 * ng + 1], a[cur][mf], b[cur][ng][2], b[cur][ng][3]);
                }
        }
    }
#undef LD_FRAGS

    // ---- epilogue: s32 -> f32 (exact), store ----
    const int row_base = tile * BM + warp_m * 32 + (lane >> 2);
    const int col_base = warp_n * 64 + 2 * (lane & 3);
#pragma unroll
    for (int mf = 0; mf < 2; ++mf) {
        const int r0 = row_base + mf * 16;
#pragma unroll
        for (int nf = 0; nf < 8; ++nf) {
            const int c = col_base + nf * 8;
            float2 lo = make_float2((float)acc[mf][nf][0], (float)acc[mf][nf][1]);
            float2 hi = make_float2((float)acc[mf][nf][2], (float)acc[mf][nf][3]);
            *(float2*)(out + (size_t)r0 * OO + c) = lo;
            *(float2*)(out + (size_t)(r0 + 8) * OO + c) = hi;
        }
    }
}

// ---------------- launch ----------------
extern "C" void kernel_launch(void* const* d_in, const int* in_sizes, int n_in,
                              void* d_out, int out_size) {
    const float* x = (const float*)d_in[0];
    const float* kw = (const float*)d_in[1];
    if (n_in >= 2 && in_sizes[0] == 9 * CC * OO && in_sizes[1] == (int)((size_t)PIX * CC)) {
        const float* t = x; x = kw; kw = t;     // defensive input-order swap
    }
    float* out = (float*)d_out;

    // Unconditional (idempotent, capture-safe) — no static guards allowed.
    cudaFuncSetAttribute(k_conv, cudaFuncAttributeMaxDynamicSharedMemorySize,
                         RING * STAGE_BYTES);

    k_sign_x<<<(PIX * CC) / (256 * 16), 256>>>(x);
    k_sign_w<<<9 * 256, 256>>>(kw);
    k_conv<<<PIX / BM, 256, RING * STAGE_BYTES>>>(out);
}